// round 16
// baseline (speedup 1.0000x reference)
#include <cuda_runtime.h>
#include <cuda_fp16.h>
#include <cuda_bf16.h>
#include <math.h>
#include <stdint.h>

// ---------------------------------------------------------------------------
// xDeepFM forward.
//  L0: bf16 3-term split mma over SYMMETRIZED pairs (K=780, pad 800)
//  L1: fp16 single mma, exact j-major K (k'=j*39+i, K=7800 pad 7840)
//  L2: eliminated: pooled2 = P @ W2 (P exact fp32), P@W2 via bf16 3-term MMA.
//  R15: 48-byte n-stride B tiles (ldmatrix conflict-free).
//  R16: 512-thread blocks, 16 warps x (16m x 56n) warp tiles -> 32 warps/SM.
// ---------------------------------------------------------------------------

#define Bsz 1024
#define NUM_NUMERIC 13
#define NUM_CAT 26
#define CARD 1000
#define Mfld 39
#define Demb 10
#define Ffeat 26013
#define Rrows (Bsz * Demb)   // 10240

#define NPAD 224
#define NSTR 48                      // smem bytes per n-row (conflict-free)
#define B_HALF48 (224 * NSTR)        // 10752
#define NT 512                       // threads per MMA block
// L0 symmetric: 780 -> pad 800, split 2 x 400
#define KPAD0 800
#define SPLIT0 2
#define KPER0 (KPAD0 / SPLIT0)
// L1: K = 39*200 = 7800 -> pad 7840, split 7 x 1120 (70 ksteps, 30-wide j win)
#define KPAD1 7840
#define SPLIT1 7
#define KPER1 (KPAD1 / SPLIT1)
#define JS1 30
#define PSTR ((size_t)Rrows * NPAD)
// pooled2 GEMM: K = 7800 -> 7808, split 8 x 61 ksteps
#define KP2 7808
#define P2SPLIT 8
#define P2KSTEPS (KP2 / 16 / P2SPLIT)   // 61

// ----------------------------- scratch --------------------------------------
__device__ float g_E_dm[Rrows * Mfld];
__device__ float g_E_flat[Bsz * Mfld * Demb];
__device__ float g_linpart[27 * Bsz];
__device__ float g_pA[SPLIT0 * Rrows * NPAD];
__device__ float g_pB[SPLIT1 * Rrows * NPAD];
__device__ float g_P[Bsz * KP2];
__device__ float g_pool2[P2SPLIT * Bsz * 200];
__device__ float g_cinlogit[Bsz];
__device__ float g_h0[Bsz * 400];
__device__ float g_h1[Bsz * 400];

__device__ __nv_bfloat16 g_W0hi[KPAD0 * NPAD];
__device__ __nv_bfloat16 g_W0lo[KPAD0 * NPAD];
__device__ __half        g_W1[KPAD1 * NPAD];
__device__ __nv_bfloat16 g_W2hi[KP2 * NPAD];
__device__ __nv_bfloat16 g_W2lo[KP2 * NPAD];

// ----------------------------- helpers --------------------------------------
__device__ __forceinline__ uint32_t smem_u32(const void* p) {
    uint32_t a;
    asm("{ .reg .u64 t; cvta.to.shared.u64 t, %1; cvt.u32.u64 %0, t; }" : "=r"(a) : "l"(p));
    return a;
}
__device__ __forceinline__ void cp_async16g(void* dst, const void* src) {
    unsigned s = (unsigned)__cvta_generic_to_shared(dst);
    asm volatile("cp.async.cg.shared.global [%0], [%1], 16;\n" :: "r"(s), "l"(src));
}
#define CP_COMMIT() asm volatile("cp.async.commit_group;\n" ::: "memory")
#define CP_WAIT0()  asm volatile("cp.async.wait_group 0;\n" ::: "memory")

__device__ __forceinline__ void ldsm_x4(uint32_t& r0, uint32_t& r1, uint32_t& r2, uint32_t& r3,
                                        uint32_t saddr) {
    asm volatile("ldmatrix.sync.aligned.m8n8.x4.shared.b16 {%0,%1,%2,%3}, [%4];"
                 : "=r"(r0), "=r"(r1), "=r"(r2), "=r"(r3) : "r"(saddr));
}
__device__ __forceinline__ void ldsm_x2(uint32_t& r0, uint32_t& r1, uint32_t saddr) {
    asm volatile("ldmatrix.sync.aligned.m8n8.x2.shared.b16 {%0,%1}, [%2];"
                 : "=r"(r0), "=r"(r1) : "r"(saddr));
}
__device__ __forceinline__ void mma_bf(float* c,
                                       uint32_t a0, uint32_t a1, uint32_t a2, uint32_t a3,
                                       uint32_t b0, uint32_t b1) {
    asm volatile("mma.sync.aligned.m16n8k16.row.col.f32.bf16.bf16.f32 "
                 "{%0,%1,%2,%3},{%4,%5,%6,%7},{%8,%9},{%0,%1,%2,%3};"
                 : "+f"(c[0]), "+f"(c[1]), "+f"(c[2]), "+f"(c[3])
                 : "r"(a0), "r"(a1), "r"(a2), "r"(a3), "r"(b0), "r"(b1));
}
__device__ __forceinline__ void mma_h(float* c,
                                      uint32_t a0, uint32_t a1, uint32_t a2, uint32_t a3,
                                      uint32_t b0, uint32_t b1) {
    asm volatile("mma.sync.aligned.m16n8k16.row.col.f32.f16.f16.f32 "
                 "{%0,%1,%2,%3},{%4,%5,%6,%7},{%8,%9},{%0,%1,%2,%3};"
                 : "+f"(c[0]), "+f"(c[1]), "+f"(c[2]), "+f"(c[3])
                 : "r"(a0), "r"(a1), "r"(a2), "r"(a3), "r"(b0), "r"(b1));
}
__device__ __forceinline__ uint32_t cvt_bf16x2(float x, float y) {
    uint32_t d;
    asm("cvt.rn.bf16x2.f32 %0, %1, %2;" : "=r"(d) : "f"(y), "f"(x));
    return d;
}
__device__ __forceinline__ uint32_t cvt_f16x2(float x, float y) {
    uint32_t d;
    asm("cvt.rn.f16x2.f32 %0, %1, %2;" : "=r"(d) : "f"(y), "f"(x));
    return d;
}
// pair index p -> (i,j), i<=j
__device__ __forceinline__ void pair_from_p(int p, int& i, int& j) {
    int ii = 0, start = 0;
    while (start + (39 - ii) <= p) { start += 39 - ii; ++ii; }
    i = ii;
    j = ii + (p - start);
}
// per-lane ldmatrix base offset within one B tile (48B n-stride), warp n0=wn*56
__device__ __forceinline__ uint32_t lane_B_off(int wn, int lane) {
    return (uint32_t)((wn * 56 + (lane & 7) + ((lane >> 4) & 1) * 8) * NSTR
                      + ((lane >> 3) & 1) * 16);
}

// B fragment loads for a 16x56 warp tile: 3x ldsm_x4 (48 cols) + 1x ldsm_x2 (8).
// r[0..13]: frag f regs at r[2f], r[2f+1].
template <typename MMA_T>
struct BFrags { uint32_t r[14]; };
__device__ __forceinline__ void load_b56(uint32_t* r, uint32_t bs) {
    ldsm_x4(r[0], r[1], r[2], r[3],  bs);
    ldsm_x4(r[4], r[5], r[6], r[7],  bs + 16 * NSTR);
    ldsm_x4(r[8], r[9], r[10], r[11], bs + 32 * NSTR);
    ldsm_x2(r[12], r[13],            bs + 48 * NSTR);
}

// ===========================================================================
// embeddings (numeric) + numeric linear partial
// ===========================================================================
__global__ void numeric_kernel(const float* __restrict__ x,
                               const float* __restrict__ w_lin,
                               const float* __restrict__ W_num) {
    const int b = blockIdx.x * 128 + threadIdx.x;
    const float* xr = x + (size_t)b * Ffeat;
    float lin = 0.0f;
    #pragma unroll
    for (int f = 0; f < NUM_NUMERIC; ++f) {
        float xv = xr[f];
        lin += xv * w_lin[f];
        #pragma unroll
        for (int d = 0; d < Demb; ++d) {
            float v = xv * W_num[f * Demb + d];
            g_E_flat[b * (Mfld * Demb) + f * Demb + d] = v;
            g_E_dm[(b * Demb + d) * Mfld + f] = v;
        }
    }
    g_linpart[26 * Bsz + b] = lin;
}

// ===========================================================================
// categorical embeddings (skinny GEMMs) + per-field linear partials
// ===========================================================================
__global__ __launch_bounds__(256)
void cat_kernel(const float* __restrict__ x,
                const float* __restrict__ w_lin,
                const float* __restrict__ W_cat) {
    __shared__ float Xs[64 * 130];
    __shared__ float Ws[64 * 10];
    __shared__ float Ls[64];

    const int t    = threadIdx.x;
    const int f    = blockIdx.y;
    const int b0   = blockIdx.x * 128;
    const int r    = t & 127;
    const int half = t >> 7;
    const int d0   = half * 5;

    float acc[5] = {0.f, 0.f, 0.f, 0.f, 0.f};
    float lin = 0.0f;

    for (int k0 = 0; k0 < CARD; k0 += 64) {
        const int kc = min(64, CARD - k0);
        __syncthreads();
        for (int idx = t; idx < 128 * 64; idx += 256) {
            int rr = idx >> 6, c = idx & 63;
            float v = (c < kc) ? x[(size_t)(b0 + rr) * Ffeat + NUM_NUMERIC + f * CARD + k0 + c] : 0.0f;
            Xs[c * 130 + rr] = v;
        }
        for (int idx = t; idx < 640; idx += 256) {
            int kk = idx / 10, d = idx - kk * 10;
            Ws[idx] = (kk < kc) ? W_cat[(size_t)(f * CARD + k0 + kk) * Demb + d] : 0.0f;
        }
        if (t < 64) Ls[t] = (t < kc) ? w_lin[NUM_NUMERIC + f * CARD + k0 + t] : 0.0f;
        __syncthreads();

        #pragma unroll 8
        for (int kk = 0; kk < 64; ++kk) {
            float xv = Xs[kk * 130 + r];
            if (half == 0) lin += xv * Ls[kk];
            #pragma unroll
            for (int q = 0; q < 5; ++q) acc[q] += xv * Ws[kk * 10 + d0 + q];
        }
    }

    const int b = b0 + r;
    const int fld = NUM_NUMERIC + f;
    #pragma unroll
    for (int q = 0; q < 5; ++q) {
        int d = d0 + q;
        g_E_flat[b * (Mfld * Demb) + fld * Demb + d] = acc[q];
        g_E_dm[(b * Demb + d) * Mfld + fld] = acc[q];
    }
    if (half == 0) g_linpart[f * Bsz + b] = lin;
}

// ===========================================================================
// W converters (gmem layouts unchanged from R15)
// ===========================================================================
__global__ void convert_w0_sym(const float* __restrict__ W,
                               __nv_bfloat16* __restrict__ Whi,
                               __nv_bfloat16* __restrict__ Wlo) {
    int idx = blockIdx.x * 256 + threadIdx.x;
    if (idx >= KPAD0 * NPAD) return;
    int ks  = idx / (NPAD * 16);
    int rem = idx - ks * (NPAD * 16);
    int n   = rem >> 4;
    int kk  = rem & 15;
    int p   = ks * 16 + kk;
    float v = 0.0f;
    if (p < 780 && n < 200) {
        int i, j;
        pair_from_p(p, i, j);
        v = W[(size_t)(i * 39 + j) * 200 + n];
        if (i != j) v += W[(size_t)(j * 39 + i) * 200 + n];
    }
    __nv_bfloat16 h = __float2bfloat16_rn(v);
    Whi[idx] = h;
    Wlo[idx] = __float2bfloat16_rn(v - __bfloat162float(h));
}

__global__ void convert_w_f16(const float* __restrict__ W,
                              __half* __restrict__ Wh) {
    int idx = blockIdx.x * 256 + threadIdx.x;
    if (idx >= KPAD1 * NPAD) return;
    int ks  = idx / (NPAD * 16);
    int rem = idx - ks * (NPAD * 16);
    int n   = rem >> 4;
    int kk  = rem & 15;
    int kp  = ks * 16 + kk;
    int j   = kp / 39;
    int i   = kp - j * 39;
    float v = (j < 200 && n < 200) ? W[(size_t)(i * 200 + j) * 200 + n] : 0.0f;
    Wh[idx] = __float2half_rn(v);
}

__global__ void convert_w2_bf(const float* __restrict__ W,
                              __nv_bfloat16* __restrict__ Whi,
                              __nv_bfloat16* __restrict__ Wlo) {
    int idx = blockIdx.x * 256 + threadIdx.x;
    if (idx >= KP2 * NPAD) return;
    int ks  = idx / (NPAD * 16);
    int rem = idx - ks * (NPAD * 16);
    int n   = rem >> 4;
    int kk  = rem & 15;
    int k   = ks * 16 + kk;
    float v = (k < 7800 && n < 200) ? W[(size_t)k * 200 + n] : 0.0f;
    __nv_bfloat16 h = __float2bfloat16_rn(v);
    Whi[idx] = h;
    Wlo[idx] = __float2bfloat16_rn(v - __bfloat162float(h));
}

// ===========================================================================
// Layer-0: bf16 3-term split over symmetric pairs. 16 warps x (16m x 56n).
// ===========================================================================
__global__ void __launch_bounds__(NT, 2)
cin_sym(const __nv_bfloat16* __restrict__ Whi,
        const __nv_bfloat16* __restrict__ Wlo,
        float* __restrict__ part) {
    constexpr int NK     = KPER0 / 16;               // 25
    constexpr int B_OFF  = 64 * 39 * 4;              // 9984
    constexpr int B_STRIDE = 2 * B_HALF48;           // hi+lo
    constexpr int TAB_OFF = B_OFF + 2 * B_STRIDE;

    extern __shared__ char sm[];
    float* Es = (float*)sm;
    uint32_t* sTab = (uint32_t*)(sm + TAB_OFF);
    const uint32_t smb = smem_u32(sm);

    const int tid  = threadIdx.x;
    const int lane = tid & 31;
    const int wid  = tid >> 5;
    const int wm   = wid & 3;
    const int wn   = wid >> 2;       // 0..3, 56 cols each
    const int g    = lane >> 2;
    const int tig  = lane & 3;
    const int row0 = blockIdx.x * 64;
    const int kbase = blockIdx.y * KPER0;

    for (int idx = tid; idx < 64 * 39; idx += NT) {
        int m = idx / 39, i = idx - m * 39;
        Es[m * 39 + i] = g_E_dm[(size_t)(row0 + m) * 39 + i];
    }
    for (int t = tid; t < KPER0; t += NT) {
        int p = kbase + t;
        int i = 0, j = 0;
        if (p < 780) pair_from_p(p, i, j);
        sTab[t] = (uint32_t)i | ((uint32_t)j << 8);
    }

    auto load_B = [&](int ks, int buf) {
        char* base = sm + B_OFF + buf * B_STRIDE;
        const size_t src0 = (size_t)(kbase / 16 + ks) * (NPAD * 16);
        for (int idx = tid; idx < 896; idx += NT) {
            int half = (idx >= 448) ? 1 : 0;
            int rem  = idx - half * 448;
            int n = rem >> 1, q = rem & 1;
            const __nv_bfloat16* src = (half ? Wlo : Whi) + src0 + n * 16 + q * 8;
            cp_async16g(base + half * B_HALF48 + n * NSTR + q * 16, src);
        }
        CP_COMMIT();
    };

    load_B(0, 0);
    CP_WAIT0();
    __syncthreads();

    float acc[7][4];
    #pragma unroll
    for (int p = 0; p < 7; ++p)
        #pragma unroll
        for (int q = 0; q < 4; ++q) acc[p][q] = 0.0f;

    const int m0 = wm * 16 + g;
    const int m1 = m0 + 8;
    const uint32_t lB = lane_B_off(wn, lane);

    for (int ks = 0; ks < NK; ++ks) {
        const int buf = ks & 1;
        if (ks + 1 < NK) load_B(ks + 1, buf ^ 1);

        uint32_t ah[4], al[4];
        {
            const uint32_t* tp = sTab + ks * 16;
            uint32_t t0 = tp[tig * 2], t1 = tp[tig * 2 + 1];
            uint32_t t2 = tp[tig * 2 + 8], t3 = tp[tig * 2 + 9];
            float v00 = Es[m0 * 39 + (t0 & 0xFF)] * Es[m0 * 39 + (t0 >> 8)];
            float v01 = Es[m0 * 39 + (t1 & 0xFF)] * Es[m0 * 39 + (t1 >> 8)];
            float v02 = Es[m0 * 39 + (t2 & 0xFF)] * Es[m0 * 39 + (t2 >> 8)];
            float v03 = Es[m0 * 39 + (t3 & 0xFF)] * Es[m0 * 39 + (t3 >> 8)];
            ah[0] = cvt_bf16x2(v00, v01);
            ah[2] = cvt_bf16x2(v02, v03);
            al[0] = cvt_bf16x2(v00 - __uint_as_float(ah[0] << 16),
                               v01 - __uint_as_float(ah[0] & 0xFFFF0000u));
            al[2] = cvt_bf16x2(v02 - __uint_as_float(ah[2] << 16),
                               v03 - __uint_as_float(ah[2] & 0xFFFF0000u));
            float v10 = Es[m1 * 39 + (t0 & 0xFF)] * Es[m1 * 39 + (t0 >> 8)];
            float v11 = Es[m1 * 39 + (t1 & 0xFF)] * Es[m1 * 39 + (t1 >> 8)];
            float v12 = Es[m1 * 39 + (t2 & 0xFF)] * Es[m1 * 39 + (t2 >> 8)];
            float v13 = Es[m1 * 39 + (t3 & 0xFF)] * Es[m1 * 39 + (t3 >> 8)];
            ah[1] = cvt_bf16x2(v10, v11);
            ah[3] = cvt_bf16x2(v12, v13);
            al[1] = cvt_bf16x2(v10 - __uint_as_float(ah[1] << 16),
                               v11 - __uint_as_float(ah[1] & 0xFFFF0000u));
            al[3] = cvt_bf16x2(v12 - __uint_as_float(ah[3] << 16),
                               v13 - __uint_as_float(ah[3] & 0xFFFF0000u));
        }

        const uint32_t bs = smb + B_OFF + buf * B_STRIDE + lB;
        uint32_t rh[14], rl[14];
        load_b56(rh, bs);
        load_b56(rl, bs + B_HALF48);
        #pragma unroll
        for (int f = 0; f < 7; ++f) {
            mma_bf(acc[f], ah[0], ah[1], ah[2], ah[3], rh[2 * f], rh[2 * f + 1]);
            mma_bf(acc[f], ah[0], ah[1], ah[2], ah[3], rl[2 * f], rl[2 * f + 1]);
            mma_bf(acc[f], al[0], al[1], al[2], al[3], rh[2 * f], rh[2 * f + 1]);
        }

        CP_WAIT0();
        __syncthreads();
    }

    float* op = part + (size_t)blockIdx.y * PSTR;
    #pragma unroll
    for (int f = 0; f < 7; ++f) {
        const float* c = acc[f];
        int col = wn * 56 + f * 8 + tig * 2;
        size_t r = (size_t)(row0 + wm * 16 + g);
        *(float2*)&op[r * NPAD + col]       = make_float2(c[0], c[1]);
        *(float2*)&op[(r + 8) * NPAD + col] = make_float2(c[2], c[3]);
    }
}

// ===========================================================================
// Layer-1: fp16 single, exact j-major K. 16 warps x (16m x 56n).
// ===========================================================================
template <int NSRC>
__global__ void __launch_bounds__(NT, 2)
cin_f16(const float* __restrict__ Cmat,
        const float* __restrict__ cbias,
        const __half* __restrict__ Wh,
        float* __restrict__ part) {
    constexpr int NK     = KPER1 / 16;               // 70
    constexpr int CSTR   = JS1 + 1;                  // 31
    constexpr int ES_OFF = 64 * CSTR * 4;            // 7936
    constexpr int B_OFF  = ((ES_OFF + 64 * 39 * 4 + 127) / 128) * 128;   // 17920
    constexpr int TAB_OFF = B_OFF + 2 * B_HALF48;

    extern __shared__ char sm[];
    float* Cs = (float*)sm;
    float* Es = (float*)(sm + ES_OFF);
    uint32_t* sTab = (uint32_t*)(sm + TAB_OFF);
    const uint32_t smb = smem_u32(sm);

    const int tid  = threadIdx.x;
    const int lane = tid & 31;
    const int wid  = tid >> 5;
    const int wm   = wid & 3;
    const int wn   = wid >> 2;
    const int g    = lane >> 2;
    const int tig  = lane & 3;
    const int row0 = blockIdx.x * 64;
    const int kbase = blockIdx.y * KPER1;
    const int jbase = kbase / 39;

    for (int idx = tid; idx < 64 * JS1; idx += NT) {
        int m = idx / JS1, jj = idx - m * JS1;
        int j = jbase + jj;
        float v = 0.0f;
        if (j < 200) {
            v = cbias[j];
            size_t off = (size_t)(row0 + m) * NPAD + j;
            #pragma unroll
            for (int s = 0; s < NSRC; ++s) v += Cmat[(size_t)s * PSTR + off];
        }
        Cs[m * CSTR + jj] = v;
    }
    for (int idx = tid; idx < 64 * 39; idx += NT) {
        int m = idx / 39, i = idx - m * 39;
        Es[m * 39 + i] = g_E_dm[(size_t)(row0 + m) * 39 + i];
    }
    for (int t = tid; t < KPER1; t += NT) {
        int kg = kbase + t;
        int j = kg / 39;
        int i = kg - j * 39;
        sTab[t] = (uint32_t)i | ((uint32_t)(j - jbase) << 8);
    }

    auto load_B = [&](int ks, int buf) {
        char* base = sm + B_OFF + buf * B_HALF48;
        const size_t src0 = (size_t)(kbase / 16 + ks) * (NPAD * 16);
        for (int idx = tid; idx < 448; idx += NT) {
            int n = idx >> 1, q = idx & 1;
            const __half* src = Wh + src0 + n * 16 + q * 8;
            cp_async16g(base + n * NSTR + q * 16, src);
        }
        CP_COMMIT();
    };

    load_B(0, 0);
    CP_WAIT0();
    __syncthreads();

    float acc[7][4];
    #pragma unroll
    for (int p = 0; p < 7; ++p)
        #pragma unroll
        for (int q = 0; q < 4; ++q) acc[p][q] = 0.0f;

    const int m0 = wm * 16 + g;
    const int m1 = m0 + 8;
    const uint32_t lB = lane_B_off(wn, lane);

    for (int ks = 0; ks < NK; ++ks) {
        const int buf = ks & 1;
        if (ks + 1 < NK) load_B(ks + 1, buf ^ 1);

        uint32_t a0, a1, a2, a3;
        {
            const uint32_t* tp = sTab + ks * 16;
            uint32_t t0 = tp[tig * 2], t1 = tp[tig * 2 + 1];
            uint32_t t2 = tp[tig * 2 + 8], t3 = tp[tig * 2 + 9];
            float v00 = Es[m0 * 39 + (t0 & 0xFF)] * Cs[m0 * CSTR + (t0 >> 8)];
            float v01 = Es[m0 * 39 + (t1 & 0xFF)] * Cs[m0 * CSTR + (t1 >> 8)];
            float v02 = Es[m0 * 39 + (t2 & 0xFF)] * Cs[m0 * CSTR + (t2 >> 8)];
            float v03 = Es[m0 * 39 + (t3 & 0xFF)] * Cs[m0 * CSTR + (t3 >> 8)];
            float v10 = Es[m1 * 39 + (t0 & 0xFF)] * Cs[m1 * CSTR + (t0 >> 8)];
            float v11 = Es[m1 * 39 + (t1 & 0xFF)] * Cs[m1 * CSTR + (t1 >> 8)];
            float v12 = Es[m1 * 39 + (t2 & 0xFF)] * Cs[m1 * CSTR + (t2 >> 8)];
            float v13 = Es[m1 * 39 + (t3 & 0xFF)] * Cs[m1 * CSTR + (t3 >> 8)];
            a0 = cvt_f16x2(v00, v01);
            a1 = cvt_f16x2(v10, v11);
            a2 = cvt_f16x2(v02, v03);
            a3 = cvt_f16x2(v12, v13);
        }

        const uint32_t bs = smb + B_OFF + buf * B_HALF48 + lB;
        uint32_t r[14];
        load_b56(r, bs);
        #pragma unroll
        for (int f = 0; f < 7; ++f)
            mma_h(acc[f], a0, a1, a2, a3, r[2 * f], r[2 * f + 1]);

        CP_WAIT0();
        __syncthreads();
    }

    float* op = part + (size_t)blockIdx.y * PSTR;
    #pragma unroll
    for (int f = 0; f < 7; ++f) {
        const float* c = acc[f];
        int col = wn * 56 + f * 8 + tig * 2;
        size_t r = (size_t)(row0 + wm * 16 + g);
        *(float2*)&op[r * NPAD + col]       = make_float2(c[0], c[1]);
        *(float2*)&op[(r + 8) * NPAD + col] = make_float2(c[2], c[3]);
    }
}

// ===========================================================================
// P kernel: C1[j,d] = b1[j] + sum_s pB[s]; P[b, i*200+j] = sum_d E*C1 (fp32)
// ===========================================================================
__global__ __launch_bounds__(256)
void p_kernel(const float* __restrict__ b1) {
    __shared__ float Es_[Mfld * Demb];
    __shared__ float Cm[200 * Demb];
    const int b = blockIdx.x;
    const int tid = threadIdx.x;

    for (int t = tid; t < Mfld * Demb; t += 256)
        Es_[t] = g_E_flat[b * (Mfld * Demb) + t];
    for (int t = tid; t < 200 * Demb; t += 256) {
        int d = t / 200;
        int j = t - d * 200;
        size_t off = (size_t)(b * Demb + d) * NPAD + j;
        float v = b1[j];
        #pragma unroll
        for (int s = 0; s < SPLIT1; ++s) v += g_pB[(size_t)s * PSTR + off];
        Cm[j * Demb + d] = v;
    }
    __syncthreads();

    for (int t = tid; t < KP2; t += 256) {
        float s = 0.0f;
        if (t < Mfld * 200) {
            int i = t / 200;
            int j = t - i * 200;
            const float* e = Es_ + i * Demb;
            const float* c = Cm + j * Demb;
            #pragma unroll
            for (int d = 0; d < Demb; ++d) s += e[d] * c[d];
        }
        g_P[(size_t)b * KP2 + t] = s;
    }
}

// ===========================================================================
// pooled2 GEMM via bf16 3-term tensor MMA. 16 warps x (16m x 56n).
// ===========================================================================
__global__ void __launch_bounds__(NT, 2)
gemm_p2(const __nv_bfloat16* __restrict__ Whi,
        const __nv_bfloat16* __restrict__ Wlo,
        float* __restrict__ outp) {
    constexpr int A_STR  = 20;
    constexpr int A_BUF  = 64 * A_STR * 4;        // 5120
    constexpr int B_OFF  = 2 * A_BUF;             // 10240
    constexpr int B_STRIDE = 2 * B_HALF48;

    extern __shared__ char sm[];
    float* As = (float*)sm;
    const uint32_t smb = smem_u32(sm);

    const int tid  = threadIdx.x;
    const int lane = tid & 31;
    const int wid  = tid >> 5;
    const int wm   = wid & 3;
    const int wn   = wid >> 2;
    const int g    = lane >> 2;
    const int tig  = lane & 3;
    const int row0 = blockIdx.x * 64;
    const int kz   = blockIdx.y;
    const int ks0  = kz * P2KSTEPS;

    auto load_AB = [&](int ks, int buf) {
        if (tid < 256) {
            int row = tid >> 2, q = tid & 3;
            const float* src = g_P + (size_t)(row0 + row) * KP2 + (ks0 + ks) * 16 + q * 4;
            cp_async16g((char*)sm + buf * A_BUF + row * 80 + q * 16, src);
        }
        char* base = sm + B_OFF + buf * B_STRIDE;
        const size_t src0 = (size_t)(ks0 + ks) * (NPAD * 16);
        for (int idx = tid; idx < 896; idx += NT) {
            int half = (idx >= 448) ? 1 : 0;
            int rem  = idx - half * 448;
            int n = rem >> 1, q = rem & 1;
            const __nv_bfloat16* src = (half ? Wlo : Whi) + src0 + n * 16 + q * 8;
            cp_async16g(base + half * B_HALF48 + n * NSTR + q * 16, src);
        }
        CP_COMMIT();
    };

    load_AB(0, 0);
    CP_WAIT0();
    __syncthreads();

    float acc[7][4];
    #pragma unroll
    for (int p = 0; p < 7; ++p)
        #pragma unroll
        for (int q = 0; q < 4; ++q) acc[p][q] = 0.0f;

    const int m0 = wm * 16 + g;
    const int m1 = m0 + 8;
    const uint32_t lB = lane_B_off(wn, lane);

    for (int ks = 0; ks < P2KSTEPS; ++ks) {
        const int buf = ks & 1;
        if (ks + 1 < P2KSTEPS) load_AB(ks + 1, buf ^ 1);

        const float* Ab = As + buf * (A_BUF / 4);
        uint32_t ah[4], al[4];
        {
            int k0 = tig * 2, k1 = tig * 2 + 8;
            float v00 = Ab[m0 * A_STR + k0],     v01 = Ab[m0 * A_STR + k0 + 1];
            float v02 = Ab[m0 * A_STR + k1],     v03 = Ab[m0 * A_STR + k1 + 1];
            ah[0] = cvt_bf16x2(v00, v01);
            ah[2] = cvt_bf16x2(v02, v03);
            al[0] = cvt_bf16x2(v00 - __uint_as_float(ah[0] << 16),
                               v01 - __uint_as_float(ah[0] & 0xFFFF0000u));
            al[2] = cvt_bf16x2(v02 - __uint_as_float(ah[2] << 16),
                               v03 - __uint_as_float(ah[2] & 0xFFFF0000u));
            float v10 = Ab[m1 * A_STR + k0],     v11 = Ab[m1 * A_STR + k0 + 1];
            float v12 = Ab[m1 * A_STR + k1],     v13 = Ab[m1 * A_STR + k1 + 1];
            ah[1] = cvt_bf16x2(v10, v11);
            ah[3] = cvt_bf16x2(v12, v13);
            al[1] = cvt_bf16x2(v10 - __uint_as_float(ah[1] << 16),
                               v11 - __uint_as_float(ah[1] & 0xFFFF0000u));
            al[3] = cvt_bf16x2(v12 - __uint_as_float(ah[3] << 16),
                               v13 - __uint_as_float(ah[3] & 0xFFFF0000u));
        }

        const uint32_t bs = smb + B_OFF + buf * B_STRIDE + lB;
        uint32_t rh[14], rl[14];
        load_b56(rh, bs);
        load_b56(rl, bs + B_HALF48);
        #pragma unroll
        for (int f = 0; f < 7; ++f) {
            mma_bf(acc[f], ah[0], ah[1], ah[2], ah[3], rh[2 * f], rh[2 * f + 1]);
            mma_bf(acc[f], ah[0], ah[1], ah[2], ah[3], rl[2 * f], rl[2 * f + 1]);
            mma_bf(acc[f], al[0], al[1], al[2], al[3], rh[2 * f], rh[2 * f + 1]);
        }

        CP_WAIT0();
        __syncthreads();
    }

    float* op = outp + (size_t)kz * (Bsz * 200);
    #pragma unroll
    for (int f = 0; f < 7; ++f) {
        const float* c = acc[f];
        int col = wn * 56 + f * 8 + tig * 2;
        if (col < 200) {
            size_t r = (size_t)(row0 + wm * 16 + g);
            *(float2*)&op[r * 200 + col]       = make_float2(c[0], c[1]);
            *(float2*)&op[(r + 8) * 200 + col] = make_float2(c[2], c[3]);
        }
    }
}

// ===========================================================================
// CIN pooling + cin linear
// ===========================================================================
__global__ void pool_kernel(const float* __restrict__ cin_lin_w,
                            const float* __restrict__ b0,
                            const float* __restrict__ b1,
                            const float* __restrict__ b2) {
    const int b = blockIdx.x;
    const int tid = threadIdx.x;

    float acc = 0.0f;
    for (int j = tid; j < 2 * Demb * 200; j += 256) {
        int l = j / 2000;
        int rem = j - l * 2000;
        int d = rem / 200;
        int h = rem - d * 200;
        size_t off = (size_t)(b * Demb + d) * NPAD + h;
        float w = cin_lin_w[l * 200 + h];
        float v = 0.0f;
        if (l == 0) {
            #pragma unroll
            for (int s = 0; s < SPLIT0; ++s) v += g_pA[(size_t)s * PSTR + off];
            if (d == 0) v += Demb * b0[h];
        } else {
            #pragma unroll
            for (int s = 0; s < SPLIT1; ++s) v += g_pB[(size_t)s * PSTR + off];
            if (d == 0) v += Demb * b1[h];
        }
        acc += v * w;
    }
    for (int h = tid; h < 200; h += 256) {
        float v = Demb * b2[h];
        #pragma unroll
        for (int s = 0; s < P2SPLIT; ++s)
            v += g_pool2[(size_t)s * (Bsz * 200) + (size_t)b * 200 + h];
        acc += v * cin_lin_w[400 + h];
    }

    __shared__ float red[256];
    red[tid] = acc;
    __syncthreads();
    for (int s = 128; s > 0; s >>= 1) {
        if (tid < s) red[tid] += red[tid + s];
        __syncthreads();
    }
    if (tid == 0) g_cinlogit[b] = red[0];
}

// ===========================================================================
// DNN GEMM + optional relu
// ===========================================================================
__global__ void dnn_gemm(const float* __restrict__ A,
                         const float* __restrict__ W,
                         const float* __restrict__ bias,
                         float* __restrict__ Out,
                         int K, int relu) {
    __shared__ float As[16 * 64];
    __shared__ float Bs[16 * 40];

    const int tid = threadIdx.x;
    const int row0 = blockIdx.x * 64;
    const int n0 = blockIdx.y * 40;
    const int tx = tid & 7;
    const int ty = tid >> 3;
    const int N = 400;

    float acc[2][5];
    #pragma unroll
    for (int m = 0; m < 2; ++m)
        #pragma unroll
        for (int q = 0; q < 5; ++q) acc[m][q] = 0.0f;

    for (int k0 = 0; k0 < K; k0 += 16) {
        __syncthreads();
        for (int idx = tid; idx < 64 * 16; idx += 256) {
            int r = idx >> 4, kk = idx & 15;
            int k = k0 + kk;
            As[kk * 64 + r] = (k < K) ? A[(size_t)(row0 + r) * K + k] : 0.0f;
        }
        for (int idx = tid; idx < 16 * 40; idx += 256) {
            int kk = idx / 40, q = idx - kk * 40;
            int k = k0 + kk;
            Bs[kk * 40 + q] = (k < K) ? W[(size_t)k * N + n0 + q] : 0.0f;
        }
        __syncthreads();

        #pragma unroll
        for (int kk = 0; kk < 16; ++kk) {
            float a0 = As[kk * 64 + ty * 2 + 0];
            float a1 = As[kk * 64 + ty * 2 + 1];
            float wv[5];
            #pragma unroll
            for (int q = 0; q < 5; ++q) wv[q] = Bs[kk * 40 + tx * 5 + q];
            #pragma unroll
            for (int q = 0; q < 5; ++q) {
                acc[0][q] += a0 * wv[q];
                acc[1][q] += a1 * wv[q];
            }
        }
    }

    #pragma unroll
    for (int m = 0; m < 2; ++m) {
        int r = row0 + ty * 2 + m;
        #pragma unroll
        for (int q = 0; q < 5; ++q) {
            int n = n0 + tx * 5 + q;
            float v = acc[m][q] + bias[n];
            if (relu) v = fmaxf(v, 0.0f);
            Out[(size_t)r * N + n] = v;
        }
    }
}

// ===========================================================================
// Final: dnn linear dot + linear partials + combine + sigmoid
// ===========================================================================
__global__ void final_kernel(const float* __restrict__ b_lin,
                             const float* __restrict__ cin_lin_b,
                             const float* __restrict__ dnn_lin_w,
                             const float* __restrict__ dnn_lin_b,
                             const float* __restrict__ pred_b,
                             float* __restrict__ out) {
    const int b = blockIdx.x;
    const int tid = threadIdx.x;
    float acc = 0.0f;
    for (int k = tid; k < 400; k += 128)
        acc += g_h1[(size_t)b * 400 + k] * dnn_lin_w[k];
    for (int f = tid; f < 27; f += 128)
        acc += g_linpart[f * Bsz + b];
    __shared__ float red[128];
    red[tid] = acc;
    __syncthreads();
    for (int s = 64; s > 0; s >>= 1) {
        if (tid < s) red[tid] += red[tid + s];
        __syncthreads();
    }
    if (tid == 0) {
        float z = red[0] + b_lin[0]
                + g_cinlogit[b] + cin_lin_b[0]
                + dnn_lin_b[0] + pred_b[0];
        out[b] = 1.0f / (1.0f + expf(-z));
    }
}

// ===========================================================================
// host launcher
// ===========================================================================
extern "C" void kernel_launch(void* const* d_in, const int* in_sizes, int n_in,
                              void* d_out, int out_size) {
    const float* x         = (const float*)d_in[0];
    const float* w_lin     = (const float*)d_in[1];
    const float* b_lin     = (const float*)d_in[2];
    const float* W_num     = (const float*)d_in[3];
    const float* W_cat     = (const float*)d_in[4];
    const float* cin_w0    = (const float*)d_in[5];
    const float* cin_b0    = (const float*)d_in[6];
    const float* cin_w1    = (const float*)d_in[7];
    const float* cin_b1    = (const float*)d_in[8];
    const float* cin_w2    = (const float*)d_in[9];
    const float* cin_b2    = (const float*)d_in[10];
    const float* cin_lin_w = (const float*)d_in[11];
    const float* cin_lin_b = (const float*)d_in[12];
    const float* dnn_w0    = (const float*)d_in[13];
    const float* dnn_b0    = (const float*)d_in[14];
    const float* dnn_w1    = (const float*)d_in[15];
    const float* dnn_b1    = (const float*)d_in[16];
    const float* dnn_lin_w = (const float*)d_in[17];
    const float* dnn_lin_b = (const float*)d_in[18];
    const float* pred_b    = (const float*)d_in[19];
    float* out = (float*)d_out;

    float *p_E_dm, *p_E_flat, *p_h0, *p_h1, *p_pA, *p_pB, *p_pool2;
    cudaGetSymbolAddress((void**)&p_E_dm,   g_E_dm);
    cudaGetSymbolAddress((void**)&p_E_flat, g_E_flat);
    cudaGetSymbolAddress((void**)&p_h0,     g_h0);
    cudaGetSymbolAddress((void**)&p_h1,     g_h1);
    cudaGetSymbolAddress((void**)&p_pA,     g_pA);
    cudaGetSymbolAddress((void**)&p_pB,     g_pB);
    cudaGetSymbolAddress((void**)&p_pool2,  g_pool2);

    __nv_bfloat16 *p_W0hi, *p_W0lo, *p_W2hi, *p_W2lo;
    __half *p_W1;
    cudaGetSymbolAddress((void**)&p_W0hi, g_W0hi);
    cudaGetSymbolAddress((void**)&p_W0lo, g_W0lo);
    cudaGetSymbolAddress((void**)&p_W1,   g_W1);
    cudaGetSymbolAddress((void**)&p_W2hi, g_W2hi);
    cudaGetSymbolAddress((void**)&p_W2lo, g_W2lo);

    const int SM_SYM = 64 * 39 * 4 + 2 * (2 * B_HALF48) + KPER0 * 4;
    const int SM_F16 = ((64 * 31 * 4 + 64 * 39 * 4 + 127) / 128) * 128
                     + 2 * B_HALF48 + KPER1 * 4;
    const int SM_P2  = 2 * (64 * 20 * 4) + 2 * (2 * B_HALF48);
    cudaFuncSetAttribute(cin_sym,          cudaFuncAttributeMaxDynamicSharedMemorySize, SM_SYM);
    cudaFuncSetAttribute(cin_f16<SPLIT0>,  cudaFuncAttributeMaxDynamicSharedMemorySize, SM_F16);
    cudaFuncSetAttribute(gemm_p2,          cudaFuncAttributeMaxDynamicSharedMemorySize, SM_P2);

    const int ROWB = Rrows / 64;   // 160

    convert_w0_sym<<<(KPAD0 * NPAD + 255) / 256, 256>>>(cin_w0, p_W0hi, p_W0lo);      // 0
    numeric_kernel<<<Bsz / 128, 128>>>(x, w_lin, W_num);                              // 1
    cat_kernel<<<dim3(Bsz / 128, NUM_CAT), 256>>>(x, w_lin, W_cat);                   // 2
    cin_sym<<<dim3(ROWB, SPLIT0), NT, SM_SYM>>>(p_W0hi, p_W0lo, p_pA);                // 3 <- capture
    convert_w_f16<<<(KPAD1 * NPAD + 255) / 256, 256>>>(cin_w1, p_W1);                 // 4
    cin_f16<SPLIT0><<<dim3(ROWB, SPLIT1), NT, SM_F16>>>(p_pA, cin_b0, p_W1, p_pB);    // 5
    convert_w2_bf<<<(KP2 * NPAD + 255) / 256, 256>>>(cin_w2, p_W2hi, p_W2lo);         // 6
    p_kernel<<<Bsz, 256>>>(cin_b1);                                                   // 7
    gemm_p2<<<dim3(Bsz / 64, P2SPLIT), NT, SM_P2>>>(p_W2hi, p_W2lo, p_pool2);         // 8
    pool_kernel<<<Bsz, 256>>>(cin_lin_w, cin_b0, cin_b1, cin_b2);                     // 9
    dim3 dgrid(Bsz / 64, 400 / 40);
    dnn_gemm<<<dgrid, 256>>>(p_E_flat, dnn_w0, dnn_b0, p_h0, Mfld * Demb, 1);         // 10
    dnn_gemm<<<dgrid, 256>>>(p_h0, dnn_w1, dnn_b1, p_h1, 400, 1);                     // 11
    final_kernel<<<Bsz, 128>>>(b_lin, cin_lin_b, dnn_lin_w, dnn_lin_b, pred_b, out);  // 12
}

// round 17
// speedup vs baseline: 1.1316x; 1.1316x over previous
#include <cuda_runtime.h>
#include <cuda_fp16.h>
#include <cuda_bf16.h>
#include <math.h>
#include <stdint.h>

// ---------------------------------------------------------------------------
// xDeepFM forward.
//  L0: bf16 3-term split mma over SYMMETRIZED pairs (K=780, pad 800)
//  L1: fp16 single mma, exact j-major K (k'=j*39+i, K=7800 pad 7840)
//  L2: eliminated: pooled2 = P @ W2 (P exact fp32), P@W2 via bf16 3-term MMA.
//  R15: 48-byte n-stride B tiles (ldmatrix conflict-free). 8 warps x 16x112.
//  R17: two ksteps (K=32) per pipeline stage -> half the barriers, 2x MMA
//       run-length between syncs.
// ---------------------------------------------------------------------------

#define Bsz 1024
#define NUM_NUMERIC 13
#define NUM_CAT 26
#define CARD 1000
#define Mfld 39
#define Demb 10
#define Ffeat 26013
#define Rrows (Bsz * Demb)   // 10240

#define NPAD 224
#define NSTR 48
#define B_HALF48 (224 * NSTR)        // 10752 bytes per (kstep, half)
// L0 symmetric: 780 -> pad 800, split 2 x 400
#define KPAD0 800
#define SPLIT0 2
#define KPER0 (KPAD0 / SPLIT0)
// L1: K = 39*200 = 7800 -> pad 7840, split 7 x 1120 (70 ksteps, 30-wide j win)
#define KPAD1 7840
#define SPLIT1 7
#define KPER1 (KPAD1 / SPLIT1)
#define JS1 30
#define PSTR ((size_t)Rrows * NPAD)
// pooled2 GEMM: K = 7800 -> 7808, split 8 x 61 ksteps
#define KP2 7808
#define P2SPLIT 8
#define P2KSTEPS (KP2 / 16 / P2SPLIT)   // 61

// ----------------------------- scratch --------------------------------------
__device__ float g_E_dm[Rrows * Mfld];
__device__ float g_E_flat[Bsz * Mfld * Demb];
__device__ float g_linpart[27 * Bsz];
__device__ float g_pA[SPLIT0 * Rrows * NPAD];
__device__ float g_pB[SPLIT1 * Rrows * NPAD];
__device__ float g_P[Bsz * KP2];
__device__ float g_pool2[P2SPLIT * Bsz * 200];
__device__ float g_cinlogit[Bsz];
__device__ float g_h0[Bsz * 400];
__device__ float g_h1[Bsz * 400];

__device__ __nv_bfloat16 g_W0hi[KPAD0 * NPAD];
__device__ __nv_bfloat16 g_W0lo[KPAD0 * NPAD];
__device__ __half        g_W1[KPAD1 * NPAD];
__device__ __nv_bfloat16 g_W2hi[KP2 * NPAD];
__device__ __nv_bfloat16 g_W2lo[KP2 * NPAD];

// ----------------------------- helpers --------------------------------------
__device__ __forceinline__ uint32_t smem_u32(const void* p) {
    uint32_t a;
    asm("{ .reg .u64 t; cvta.to.shared.u64 t, %1; cvt.u32.u64 %0, t; }" : "=r"(a) : "l"(p));
    return a;
}
__device__ __forceinline__ void cp_async16g(void* dst, const void* src) {
    unsigned s = (unsigned)__cvta_generic_to_shared(dst);
    asm volatile("cp.async.cg.shared.global [%0], [%1], 16;\n" :: "r"(s), "l"(src));
}
#define CP_COMMIT() asm volatile("cp.async.commit_group;\n" ::: "memory")
#define CP_WAIT0()  asm volatile("cp.async.wait_group 0;\n" ::: "memory")

__device__ __forceinline__ void ldsm_x4(uint32_t& r0, uint32_t& r1, uint32_t& r2, uint32_t& r3,
                                        uint32_t saddr) {
    asm volatile("ldmatrix.sync.aligned.m8n8.x4.shared.b16 {%0,%1,%2,%3}, [%4];"
                 : "=r"(r0), "=r"(r1), "=r"(r2), "=r"(r3) : "r"(saddr));
}
__device__ __forceinline__ void mma_bf(float* c,
                                       uint32_t a0, uint32_t a1, uint32_t a2, uint32_t a3,
                                       uint32_t b0, uint32_t b1) {
    asm volatile("mma.sync.aligned.m16n8k16.row.col.f32.bf16.bf16.f32 "
                 "{%0,%1,%2,%3},{%4,%5,%6,%7},{%8,%9},{%0,%1,%2,%3};"
                 : "+f"(c[0]), "+f"(c[1]), "+f"(c[2]), "+f"(c[3])
                 : "r"(a0), "r"(a1), "r"(a2), "r"(a3), "r"(b0), "r"(b1));
}
__device__ __forceinline__ void mma_h(float* c,
                                      uint32_t a0, uint32_t a1, uint32_t a2, uint32_t a3,
                                      uint32_t b0, uint32_t b1) {
    asm volatile("mma.sync.aligned.m16n8k16.row.col.f32.f16.f16.f32 "
                 "{%0,%1,%2,%3},{%4,%5,%6,%7},{%8,%9},{%0,%1,%2,%3};"
                 : "+f"(c[0]), "+f"(c[1]), "+f"(c[2]), "+f"(c[3])
                 : "r"(a0), "r"(a1), "r"(a2), "r"(a3), "r"(b0), "r"(b1));
}
__device__ __forceinline__ uint32_t cvt_bf16x2(float x, float y) {
    uint32_t d;
    asm("cvt.rn.bf16x2.f32 %0, %1, %2;" : "=r"(d) : "f"(y), "f"(x));
    return d;
}
__device__ __forceinline__ uint32_t cvt_f16x2(float x, float y) {
    uint32_t d;
    asm("cvt.rn.f16x2.f32 %0, %1, %2;" : "=r"(d) : "f"(y), "f"(x));
    return d;
}
// pair index p -> (i,j), i<=j
__device__ __forceinline__ void pair_from_p(int p, int& i, int& j) {
    int ii = 0, start = 0;
    while (start + (39 - ii) <= p) { start += 39 - ii; ++ii; }
    i = ii;
    j = ii + (p - start);
}
// per-lane ldmatrix base offset within one B tile (48B n-stride), warp n0=wn*112
__device__ __forceinline__ uint32_t lane_B_off(int wn, int lane) {
    return (uint32_t)((wn * 112 + (lane & 7) + ((lane >> 4) & 1) * 8) * NSTR
                      + ((lane >> 3) & 1) * 16);
}

// ===========================================================================
// embeddings (numeric) + numeric linear partial
// ===========================================================================
__global__ void numeric_kernel(const float* __restrict__ x,
                               const float* __restrict__ w_lin,
                               const float* __restrict__ W_num) {
    const int b = blockIdx.x * 128 + threadIdx.x;
    const float* xr = x + (size_t)b * Ffeat;
    float lin = 0.0f;
    #pragma unroll
    for (int f = 0; f < NUM_NUMERIC; ++f) {
        float xv = xr[f];
        lin += xv * w_lin[f];
        #pragma unroll
        for (int d = 0; d < Demb; ++d) {
            float v = xv * W_num[f * Demb + d];
            g_E_flat[b * (Mfld * Demb) + f * Demb + d] = v;
            g_E_dm[(b * Demb + d) * Mfld + f] = v;
        }
    }
    g_linpart[26 * Bsz + b] = lin;
}

// ===========================================================================
// categorical embeddings (skinny GEMMs) + per-field linear partials
// ===========================================================================
__global__ __launch_bounds__(256)
void cat_kernel(const float* __restrict__ x,
                const float* __restrict__ w_lin,
                const float* __restrict__ W_cat) {
    __shared__ float Xs[64 * 130];
    __shared__ float Ws[64 * 10];
    __shared__ float Ls[64];

    const int t    = threadIdx.x;
    const int f    = blockIdx.y;
    const int b0   = blockIdx.x * 128;
    const int r    = t & 127;
    const int half = t >> 7;
    const int d0   = half * 5;

    float acc[5] = {0.f, 0.f, 0.f, 0.f, 0.f};
    float lin = 0.0f;

    for (int k0 = 0; k0 < CARD; k0 += 64) {
        const int kc = min(64, CARD - k0);
        __syncthreads();
        for (int idx = t; idx < 128 * 64; idx += 256) {
            int rr = idx >> 6, c = idx & 63;
            float v = (c < kc) ? x[(size_t)(b0 + rr) * Ffeat + NUM_NUMERIC + f * CARD + k0 + c] : 0.0f;
            Xs[c * 130 + rr] = v;
        }
        for (int idx = t; idx < 640; idx += 256) {
            int kk = idx / 10, d = idx - kk * 10;
            Ws[idx] = (kk < kc) ? W_cat[(size_t)(f * CARD + k0 + kk) * Demb + d] : 0.0f;
        }
        if (t < 64) Ls[t] = (t < kc) ? w_lin[NUM_NUMERIC + f * CARD + k0 + t] : 0.0f;
        __syncthreads();

        #pragma unroll 8
        for (int kk = 0; kk < 64; ++kk) {
            float xv = Xs[kk * 130 + r];
            if (half == 0) lin += xv * Ls[kk];
            #pragma unroll
            for (int q = 0; q < 5; ++q) acc[q] += xv * Ws[kk * 10 + d0 + q];
        }
    }

    const int b = b0 + r;
    const int fld = NUM_NUMERIC + f;
    #pragma unroll
    for (int q = 0; q < 5; ++q) {
        int d = d0 + q;
        g_E_flat[b * (Mfld * Demb) + fld * Demb + d] = acc[q];
        g_E_dm[(b * Demb + d) * Mfld + fld] = acc[q];
    }
    if (half == 0) g_linpart[f * Bsz + b] = lin;
}

// ===========================================================================
// W converters (gmem layouts unchanged)
// ===========================================================================
__global__ void convert_w0_sym(const float* __restrict__ W,
                               __nv_bfloat16* __restrict__ Whi,
                               __nv_bfloat16* __restrict__ Wlo) {
    int idx = blockIdx.x * 256 + threadIdx.x;
    if (idx >= KPAD0 * NPAD) return;
    int ks  = idx / (NPAD * 16);
    int rem = idx - ks * (NPAD * 16);
    int n   = rem >> 4;
    int kk  = rem & 15;
    int p   = ks * 16 + kk;
    float v = 0.0f;
    if (p < 780 && n < 200) {
        int i, j;
        pair_from_p(p, i, j);
        v = W[(size_t)(i * 39 + j) * 200 + n];
        if (i != j) v += W[(size_t)(j * 39 + i) * 200 + n];
    }
    __nv_bfloat16 h = __float2bfloat16_rn(v);
    Whi[idx] = h;
    Wlo[idx] = __float2bfloat16_rn(v - __bfloat162float(h));
}

__global__ void convert_w_f16(const float* __restrict__ W,
                              __half* __restrict__ Wh) {
    int idx = blockIdx.x * 256 + threadIdx.x;
    if (idx >= KPAD1 * NPAD) return;
    int ks  = idx / (NPAD * 16);
    int rem = idx - ks * (NPAD * 16);
    int n   = rem >> 4;
    int kk  = rem & 15;
    int kp  = ks * 16 + kk;
    int j   = kp / 39;
    int i   = kp - j * 39;
    float v = (j < 200 && n < 200) ? W[(size_t)(i * 200 + j) * 200 + n] : 0.0f;
    Wh[idx] = __float2half_rn(v);
}

__global__ void convert_w2_bf(const float* __restrict__ W,
                              __nv_bfloat16* __restrict__ Whi,
                              __nv_bfloat16* __restrict__ Wlo) {
    int idx = blockIdx.x * 256 + threadIdx.x;
    if (idx >= KP2 * NPAD) return;
    int ks  = idx / (NPAD * 16);
    int rem = idx - ks * (NPAD * 16);
    int n   = rem >> 4;
    int kk  = rem & 15;
    int k   = ks * 16 + kk;
    float v = (k < 7800 && n < 200) ? W[(size_t)k * 200 + n] : 0.0f;
    __nv_bfloat16 h = __float2bfloat16_rn(v);
    Whi[idx] = h;
    Wlo[idx] = __float2bfloat16_rn(v - __bfloat162float(h));
}

// ===========================================================================
// Layer-0: bf16 3-term split over symmetric pairs. 2 ksteps per stage.
// ===========================================================================
__global__ void __launch_bounds__(256, 2)
cin_sym(const __nv_bfloat16* __restrict__ Whi,
        const __nv_bfloat16* __restrict__ Wlo,
        float* __restrict__ part) {
    constexpr int NK     = KPER0 / 16;               // 25
    constexpr int B_OFF  = 64 * 39 * 4;              // 9984
    constexpr int KS_BYTES = 2 * B_HALF48;           // hi+lo per kstep = 21504
    constexpr int BUF_BYTES = 2 * KS_BYTES;          // 2 ksteps = 43008
    constexpr int TAB_OFF = B_OFF + 2 * BUF_BYTES;   // 96000

    extern __shared__ char sm[];
    float* Es = (float*)sm;
    uint32_t* sTab = (uint32_t*)(sm + TAB_OFF);
    const uint32_t smb = smem_u32(sm);

    const int tid  = threadIdx.x;
    const int lane = tid & 31;
    const int wid  = tid >> 5;
    const int wm   = wid & 3;
    const int wn   = wid >> 2;
    const int g    = lane >> 2;
    const int tig  = lane & 3;
    const int row0 = blockIdx.x * 64;
    const int kbase = blockIdx.y * KPER0;

    for (int idx = tid; idx < 64 * 39; idx += 256) {
        int m = idx / 39, i = idx - m * 39;
        Es[m * 39 + i] = g_E_dm[(size_t)(row0 + m) * 39 + i];
    }
    for (int t = tid; t < KPER0; t += 256) {
        int p = kbase + t;
        int i = 0, j = 0;
        if (p < 780) pair_from_p(p, i, j);
        sTab[t] = (uint32_t)i | ((uint32_t)j << 8);
    }

    auto load_B2 = [&](int k0, int buf) {
        char* base = sm + B_OFF + buf * BUF_BYTES;
        #pragma unroll
        for (int s = 0; s < 2; ++s) {
            if (k0 + s >= NK) break;
            const size_t src0 = (size_t)(kbase / 16 + k0 + s) * (NPAD * 16);
            for (int idx = tid; idx < 896; idx += 256) {
                int half = (idx >= 448) ? 1 : 0;
                int rem  = idx - half * 448;
                int n = rem >> 1, q = rem & 1;
                const __nv_bfloat16* src = (half ? Wlo : Whi) + src0 + n * 16 + q * 8;
                cp_async16g(base + s * KS_BYTES + half * B_HALF48 + n * NSTR + q * 16, src);
            }
        }
        CP_COMMIT();
    };

    load_B2(0, 0);
    CP_WAIT0();
    __syncthreads();

    float acc[14][4];
    #pragma unroll
    for (int p = 0; p < 14; ++p)
        #pragma unroll
        for (int q = 0; q < 4; ++q) acc[p][q] = 0.0f;

    const int m0 = wm * 16 + g;
    const int m1 = m0 + 8;
    const uint32_t lB = lane_B_off(wn, lane);

    for (int kp = 0; kp < NK; kp += 2) {
        const int buf = (kp >> 1) & 1;
        if (kp + 2 < NK) load_B2(kp + 2, buf ^ 1);

        #pragma unroll
        for (int s = 0; s < 2; ++s) {
            const int ks = kp + s;
            if (ks >= NK) break;

            uint32_t ah[4], al[4];
            {
                const uint32_t* tp = sTab + ks * 16;
                uint32_t t0 = tp[tig * 2], t1 = tp[tig * 2 + 1];
                uint32_t t2 = tp[tig * 2 + 8], t3 = tp[tig * 2 + 9];
                float v00 = Es[m0 * 39 + (t0 & 0xFF)] * Es[m0 * 39 + (t0 >> 8)];
                float v01 = Es[m0 * 39 + (t1 & 0xFF)] * Es[m0 * 39 + (t1 >> 8)];
                float v02 = Es[m0 * 39 + (t2 & 0xFF)] * Es[m0 * 39 + (t2 >> 8)];
                float v03 = Es[m0 * 39 + (t3 & 0xFF)] * Es[m0 * 39 + (t3 >> 8)];
                float v10 = Es[m1 * 39 + (t0 & 0xFF)] * Es[m1 * 39 + (t0 >> 8)];
                float v11 = Es[m1 * 39 + (t1 & 0xFF)] * Es[m1 * 39 + (t1 >> 8)];
                float v12 = Es[m1 * 39 + (t2 & 0xFF)] * Es[m1 * 39 + (t2 >> 8)];
                float v13 = Es[m1 * 39 + (t3 & 0xFF)] * Es[m1 * 39 + (t3 >> 8)];
                ah[0] = cvt_bf16x2(v00, v01);
                ah[1] = cvt_bf16x2(v10, v11);
                ah[2] = cvt_bf16x2(v02, v03);
                ah[3] = cvt_bf16x2(v12, v13);
                al[0] = cvt_bf16x2(v00 - __uint_as_float(ah[0] << 16),
                                   v01 - __uint_as_float(ah[0] & 0xFFFF0000u));
                al[1] = cvt_bf16x2(v10 - __uint_as_float(ah[1] << 16),
                                   v11 - __uint_as_float(ah[1] & 0xFFFF0000u));
                al[2] = cvt_bf16x2(v02 - __uint_as_float(ah[2] << 16),
                                   v03 - __uint_as_float(ah[2] & 0xFFFF0000u));
                al[3] = cvt_bf16x2(v12 - __uint_as_float(ah[3] << 16),
                                   v13 - __uint_as_float(ah[3] & 0xFFFF0000u));
            }

            const uint32_t bs = smb + B_OFF + buf * BUF_BYTES + s * KS_BYTES + lB;
            #pragma unroll
            for (int nt = 0; nt < 7; ++nt) {
                uint32_t r0, r1, r2, r3, s0, s1, s2, s3;
                ldsm_x4(r0, r1, r2, r3, bs + nt * (16 * NSTR));
                ldsm_x4(s0, s1, s2, s3, bs + B_HALF48 + nt * (16 * NSTR));
                mma_bf(acc[nt * 2],     ah[0], ah[1], ah[2], ah[3], r0, r1);
                mma_bf(acc[nt * 2 + 1], ah[0], ah[1], ah[2], ah[3], r2, r3);
                mma_bf(acc[nt * 2],     ah[0], ah[1], ah[2], ah[3], s0, s1);
                mma_bf(acc[nt * 2 + 1], ah[0], ah[1], ah[2], ah[3], s2, s3);
                mma_bf(acc[nt * 2],     al[0], al[1], al[2], al[3], r0, r1);
                mma_bf(acc[nt * 2 + 1], al[0], al[1], al[2], al[3], r2, r3);
            }
        }

        CP_WAIT0();
        __syncthreads();
    }

    float* op = part + (size_t)blockIdx.y * PSTR;
    #pragma unroll
    for (int nt = 0; nt < 7; ++nt)
        #pragma unroll
        for (int nh = 0; nh < 2; ++nh) {
            const float* c = acc[nt * 2 + nh];
            int col = wn * 112 + nt * 16 + nh * 8 + tig * 2;
            size_t r = (size_t)(row0 + wm * 16 + g);
            *(float2*)&op[r * NPAD + col]       = make_float2(c[0], c[1]);
            *(float2*)&op[(r + 8) * NPAD + col] = make_float2(c[2], c[3]);
        }
}

// ===========================================================================
// Layer-1: fp16 single, exact j-major K. 2 ksteps per stage.
// ===========================================================================
template <int NSRC>
__global__ void __launch_bounds__(256, 2)
cin_f16(const float* __restrict__ Cmat,
        const float* __restrict__ cbias,
        const __half* __restrict__ Wh,
        float* __restrict__ part) {
    constexpr int NK     = KPER1 / 16;               // 70 (even)
    constexpr int CSTR   = JS1 + 1;                  // 31
    constexpr int ES_OFF = 64 * CSTR * 4;            // 7936
    constexpr int B_OFF  = ((ES_OFF + 64 * 39 * 4 + 127) / 128) * 128;   // 17920
    constexpr int BUF_BYTES = 2 * B_HALF48;          // 2 ksteps (single prec)
    constexpr int TAB_OFF = B_OFF + 2 * BUF_BYTES;   // 60928

    extern __shared__ char sm[];
    float* Cs = (float*)sm;
    float* Es = (float*)(sm + ES_OFF);
    uint32_t* sTab = (uint32_t*)(sm + TAB_OFF);
    const uint32_t smb = smem_u32(sm);

    const int tid  = threadIdx.x;
    const int lane = tid & 31;
    const int wid  = tid >> 5;
    const int wm   = wid & 3;
    const int wn   = wid >> 2;
    const int g    = lane >> 2;
    const int tig  = lane & 3;
    const int row0 = blockIdx.x * 64;
    const int kbase = blockIdx.y * KPER1;
    const int jbase = kbase / 39;

    for (int idx = tid; idx < 64 * JS1; idx += 256) {
        int m = idx / JS1, jj = idx - m * JS1;
        int j = jbase + jj;
        float v = 0.0f;
        if (j < 200) {
            v = cbias[j];
            size_t off = (size_t)(row0 + m) * NPAD + j;
            #pragma unroll
            for (int s = 0; s < NSRC; ++s) v += Cmat[(size_t)s * PSTR + off];
        }
        Cs[m * CSTR + jj] = v;
    }
    for (int idx = tid; idx < 64 * 39; idx += 256) {
        int m = idx / 39, i = idx - m * 39;
        Es[m * 39 + i] = g_E_dm[(size_t)(row0 + m) * 39 + i];
    }
    for (int t = tid; t < KPER1; t += 256) {
        int kg = kbase + t;
        int j = kg / 39;
        int i = kg - j * 39;
        sTab[t] = (uint32_t)i | ((uint32_t)(j - jbase) << 8);
    }

    auto load_B2 = [&](int k0, int buf) {
        char* base = sm + B_OFF + buf * BUF_BYTES;
        #pragma unroll
        for (int s = 0; s < 2; ++s) {
            const size_t src0 = (size_t)(kbase / 16 + k0 + s) * (NPAD * 16);
            for (int idx = tid; idx < 448; idx += 256) {
                int n = idx >> 1, q = idx & 1;
                const __half* src = Wh + src0 + n * 16 + q * 8;
                cp_async16g(base + s * B_HALF48 + n * NSTR + q * 16, src);
            }
        }
        CP_COMMIT();
    };

    load_B2(0, 0);
    CP_WAIT0();
    __syncthreads();

    float acc[14][4];
    #pragma unroll
    for (int p = 0; p < 14; ++p)
        #pragma unroll
        for (int q = 0; q < 4; ++q) acc[p][q] = 0.0f;

    const int m0 = wm * 16 + g;
    const int m1 = m0 + 8;
    const uint32_t lB = lane_B_off(wn, lane);

    for (int kp = 0; kp < NK; kp += 2) {
        const int buf = (kp >> 1) & 1;
        if (kp + 2 < NK) load_B2(kp + 2, buf ^ 1);

        #pragma unroll
        for (int s = 0; s < 2; ++s) {
            const int ks = kp + s;

            uint32_t a0, a1, a2, a3;
            {
                const uint32_t* tp = sTab + ks * 16;
                uint32_t t0 = tp[tig * 2], t1 = tp[tig * 2 + 1];
                uint32_t t2 = tp[tig * 2 + 8], t3 = tp[tig * 2 + 9];
                float v00 = Es[m0 * 39 + (t0 & 0xFF)] * Cs[m0 * CSTR + (t0 >> 8)];
                float v01 = Es[m0 * 39 + (t1 & 0xFF)] * Cs[m0 * CSTR + (t1 >> 8)];
                float v02 = Es[m0 * 39 + (t2 & 0xFF)] * Cs[m0 * CSTR + (t2 >> 8)];
                float v03 = Es[m0 * 39 + (t3 & 0xFF)] * Cs[m0 * CSTR + (t3 >> 8)];
                float v10 = Es[m1 * 39 + (t0 & 0xFF)] * Cs[m1 * CSTR + (t0 >> 8)];
                float v11 = Es[m1 * 39 + (t1 & 0xFF)] * Cs[m1 * CSTR + (t1 >> 8)];
                float v12 = Es[m1 * 39 + (t2 & 0xFF)] * Cs[m1 * CSTR + (t2 >> 8)];
                float v13 = Es[m1 * 39 + (t3 & 0xFF)] * Cs[m1 * CSTR + (t3 >> 8)];
                a0 = cvt_f16x2(v00, v01);
                a1 = cvt_f16x2(v10, v11);
                a2 = cvt_f16x2(v02, v03);
                a3 = cvt_f16x2(v12, v13);
            }

            const uint32_t bs = smb + B_OFF + buf * BUF_BYTES + s * B_HALF48 + lB;
            #pragma unroll
            for (int nt = 0; nt < 7; ++nt) {
                uint32_t r0, r1, r2, r3;
                ldsm_x4(r0, r1, r2, r3, bs + nt * (16 * NSTR));
                mma_h(acc[nt * 2],     a0, a1, a2, a3, r0, r1);
                mma_h(acc[nt * 2 + 1], a0, a1, a2, a3, r2, r3);
            }
        }

        CP_WAIT0();
        __syncthreads();
    }

    float* op = part + (size_t)blockIdx.y * PSTR;
    #pragma unroll
    for (int nt = 0; nt < 7; ++nt)
        #pragma unroll
        for (int nh = 0; nh < 2; ++nh) {
            const float* c = acc[nt * 2 + nh];
            int col = wn * 112 + nt * 16 + nh * 8 + tig * 2;
            size_t r = (size_t)(row0 + wm * 16 + g);
            *(float2*)&op[r * NPAD + col]       = make_float2(c[0], c[1]);
            *(float2*)&op[(r + 8) * NPAD + col] = make_float2(c[2], c[3]);
        }
}

// ===========================================================================
// P kernel: C1[j,d] = b1[j] + sum_s pB[s]; P[b, i*200+j] = sum_d E*C1 (fp32)
// ===========================================================================
__global__ __launch_bounds__(256)
void p_kernel(const float* __restrict__ b1) {
    __shared__ float Es_[Mfld * Demb];
    __shared__ float Cm[200 * Demb];
    const int b = blockIdx.x;
    const int tid = threadIdx.x;

    for (int t = tid; t < Mfld * Demb; t += 256)
        Es_[t] = g_E_flat[b * (Mfld * Demb) + t];
    for (int t = tid; t < 200 * Demb; t += 256) {
        int d = t / 200;
        int j = t - d * 200;
        size_t off = (size_t)(b * Demb + d) * NPAD + j;
        float v = b1[j];
        #pragma unroll
        for (int s = 0; s < SPLIT1; ++s) v += g_pB[(size_t)s * PSTR + off];
        Cm[j * Demb + d] = v;
    }
    __syncthreads();

    for (int t = tid; t < KP2; t += 256) {
        float s = 0.0f;
        if (t < Mfld * 200) {
            int i = t / 200;
            int j = t - i * 200;
            const float* e = Es_ + i * Demb;
            const float* c = Cm + j * Demb;
            #pragma unroll
            for (int d = 0; d < Demb; ++d) s += e[d] * c[d];
        }
        g_P[(size_t)b * KP2 + t] = s;
    }
}

// ===========================================================================
// pooled2 GEMM via bf16 3-term tensor MMA. 2 ksteps per stage.
// ===========================================================================
__global__ void __launch_bounds__(256, 2)
gemm_p2(const __nv_bfloat16* __restrict__ Whi,
        const __nv_bfloat16* __restrict__ Wlo,
        float* __restrict__ outp) {
    constexpr int A_STR  = 20;
    constexpr int A_KS   = 64 * A_STR * 4;        // 5120 per kstep
    constexpr int A_BUF  = 2 * A_KS;              // 2 ksteps = 10240
    constexpr int B_OFF  = 2 * A_BUF;             // 20480
    constexpr int KS_BYTES = 2 * B_HALF48;        // 21504
    constexpr int BUF_BYTES = 2 * KS_BYTES;       // 43008

    extern __shared__ char sm[];
    float* As = (float*)sm;
    const uint32_t smb = smem_u32(sm);

    const int tid  = threadIdx.x;
    const int lane = tid & 31;
    const int wid  = tid >> 5;
    const int wm   = wid & 3;
    const int wn   = wid >> 2;
    const int g    = lane >> 2;
    const int tig  = lane & 3;
    const int row0 = blockIdx.x * 64;
    const int kz   = blockIdx.y;
    const int ks0  = kz * P2KSTEPS;

    auto load_AB2 = [&](int k0, int buf) {
        #pragma unroll
        for (int s = 0; s < 2; ++s) {
            if (k0 + s >= P2KSTEPS) break;
            {
                int row = tid >> 2, q = tid & 3;
                const float* src = g_P + (size_t)(row0 + row) * KP2 + (ks0 + k0 + s) * 16 + q * 4;
                cp_async16g((char*)sm + buf * A_BUF + s * A_KS + row * 80 + q * 16, src);
            }
            char* base = sm + B_OFF + buf * BUF_BYTES + s * KS_BYTES;
            const size_t src0 = (size_t)(ks0 + k0 + s) * (NPAD * 16);
            for (int idx = tid; idx < 896; idx += 256) {
                int half = (idx >= 448) ? 1 : 0;
                int rem  = idx - half * 448;
                int n = rem >> 1, q = rem & 1;
                const __nv_bfloat16* src = (half ? Wlo : Whi) + src0 + n * 16 + q * 8;
                cp_async16g(base + half * B_HALF48 + n * NSTR + q * 16, src);
            }
        }
        CP_COMMIT();
    };

    load_AB2(0, 0);
    CP_WAIT0();
    __syncthreads();

    float acc[14][4];
    #pragma unroll
    for (int p = 0; p < 14; ++p)
        #pragma unroll
        for (int q = 0; q < 4; ++q) acc[p][q] = 0.0f;

    const int m0 = wm * 16 + g;
    const int m1 = m0 + 8;
    const uint32_t lB = lane_B_off(wn, lane);

    for (int kp = 0; kp < P2KSTEPS; kp += 2) {
        const int buf = (kp >> 1) & 1;
        if (kp + 2 < P2KSTEPS) load_AB2(kp + 2, buf ^ 1);

        #pragma unroll
        for (int s = 0; s < 2; ++s) {
            const int ks = kp + s;
            if (ks >= P2KSTEPS) break;

            const float* Ab = As + (buf * 2 + s) * (A_KS / 4);
            uint32_t ah[4], al[4];
            {
                int k0 = tig * 2, k1 = tig * 2 + 8;
                float v00 = Ab[m0 * A_STR + k0],     v01 = Ab[m0 * A_STR + k0 + 1];
                float v02 = Ab[m0 * A_STR + k1],     v03 = Ab[m0 * A_STR + k1 + 1];
                float v10 = Ab[m1 * A_STR + k0],     v11 = Ab[m1 * A_STR + k0 + 1];
                float v12 = Ab[m1 * A_STR + k1],     v13 = Ab[m1 * A_STR + k1 + 1];
                ah[0] = cvt_bf16x2(v00, v01);
                ah[1] = cvt_bf16x2(v10, v11);
                ah[2] = cvt_bf16x2(v02, v03);
                ah[3] = cvt_bf16x2(v12, v13);
                al[0] = cvt_bf16x2(v00 - __uint_as_float(ah[0] << 16),
                                   v01 - __uint_as_float(ah[0] & 0xFFFF0000u));
                al[1] = cvt_bf16x2(v10 - __uint_as_float(ah[1] << 16),
                                   v11 - __uint_as_float(ah[1] & 0xFFFF0000u));
                al[2] = cvt_bf16x2(v02 - __uint_as_float(ah[2] << 16),
                                   v03 - __uint_as_float(ah[2] & 0xFFFF0000u));
                al[3] = cvt_bf16x2(v12 - __uint_as_float(ah[3] << 16),
                                   v13 - __uint_as_float(ah[3] & 0xFFFF0000u));
            }

            const uint32_t bs = smb + B_OFF + buf * BUF_BYTES + s * KS_BYTES + lB;
            #pragma unroll
            for (int nt = 0; nt < 7; ++nt) {
                uint32_t r0, r1, r2, r3, s0, s1, s2, s3;
                ldsm_x4(r0, r1, r2, r3, bs + nt * (16 * NSTR));
                ldsm_x4(s0, s1, s2, s3, bs + B_HALF48 + nt * (16 * NSTR));
                mma_bf(acc[nt * 2],     ah[0], ah[1], ah[2], ah[3], r0, r1);
                mma_bf(acc[nt * 2 + 1], ah[0], ah[1], ah[2], ah[3], r2, r3);
                mma_bf(acc[nt * 2],     ah[0], ah[1], ah[2], ah[3], s0, s1);
                mma_bf(acc[nt * 2 + 1], ah[0], ah[1], ah[2], ah[3], s2, s3);
                mma_bf(acc[nt * 2],     al[0], al[1], al[2], al[3], r0, r1);
                mma_bf(acc[nt * 2 + 1], al[0], al[1], al[2], al[3], r2, r3);
            }
        }

        CP_WAIT0();
        __syncthreads();
    }

    float* op = outp + (size_t)kz * (Bsz * 200);
    #pragma unroll
    for (int nt = 0; nt < 7; ++nt)
        #pragma unroll
        for (int nh = 0; nh < 2; ++nh) {
            const float* c = acc[nt * 2 + nh];
            int col = wn * 112 + nt * 16 + nh * 8 + tig * 2;
            if (col < 200) {
                size_t r = (size_t)(row0 + wm * 16 + g);
                *(float2*)&op[r * 200 + col]       = make_float2(c[0], c[1]);
                *(float2*)&op[(r + 8) * 200 + col] = make_float2(c[2], c[3]);
            }
        }
}

// ===========================================================================
// CIN pooling + cin linear
// ===========================================================================
__global__ void pool_kernel(const float* __restrict__ cin_lin_w,
                            const float* __restrict__ b0,
                            const float* __restrict__ b1,
                            const float* __restrict__ b2) {
    const int b = blockIdx.x;
    const int tid = threadIdx.x;

    float acc = 0.0f;
    for (int j = tid; j < 2 * Demb * 200; j += 256) {
        int l = j / 2000;
        int rem = j - l * 2000;
        int d = rem / 200;
        int h = rem - d * 200;
        size_t off = (size_t)(b * Demb + d) * NPAD + h;
        float w = cin_lin_w[l * 200 + h];
        float v = 0.0f;
        if (l == 0) {
            #pragma unroll
            for (int s = 0; s < SPLIT0; ++s) v += g_pA[(size_t)s * PSTR + off];
            if (d == 0) v += Demb * b0[h];
        } else {
            #pragma unroll
            for (int s = 0; s < SPLIT1; ++s) v += g_pB[(size_t)s * PSTR + off];
            if (d == 0) v += Demb * b1[h];
        }
        acc += v * w;
    }
    for (int h = tid; h < 200; h += 256) {
        float v = Demb * b2[h];
        #pragma unroll
        for (int s = 0; s < P2SPLIT; ++s)
            v += g_pool2[(size_t)s * (Bsz * 200) + (size_t)b * 200 + h];
        acc += v * cin_lin_w[400 + h];
    }

    __shared__ float red[256];
    red[tid] = acc;
    __syncthreads();
    for (int s = 128; s > 0; s >>= 1) {
        if (tid < s) red[tid] += red[tid + s];
        __syncthreads();
    }
    if (tid == 0) g_cinlogit[b] = red[0];
}

// ===========================================================================
// DNN GEMM + optional relu
// ===========================================================================
__global__ void dnn_gemm(const float* __restrict__ A,
                         const float* __restrict__ W,
                         const float* __restrict__ bias,
                         float* __restrict__ Out,
                         int K, int relu) {
    __shared__ float As[16 * 64];
    __shared__ float Bs[16 * 40];

    const int tid = threadIdx.x;
    const int row0 = blockIdx.x * 64;
    const int n0 = blockIdx.y * 40;
    const int tx = tid & 7;
    const int ty = tid >> 3;
    const int N = 400;

    float acc[2][5];
    #pragma unroll
    for (int m = 0; m < 2; ++m)
        #pragma unroll
        for (int q = 0; q < 5; ++q) acc[m][q] = 0.0f;

    for (int k0 = 0; k0 < K; k0 += 16) {
        __syncthreads();
        for (int idx = tid; idx < 64 * 16; idx += 256) {
            int r = idx >> 4, kk = idx & 15;
            int k = k0 + kk;
            As[kk * 64 + r] = (k < K) ? A[(size_t)(row0 + r) * K + k] : 0.0f;
        }
        for (int idx = tid; idx < 16 * 40; idx += 256) {
            int kk = idx / 40, q = idx - kk * 40;
            int k = k0 + kk;
            Bs[kk * 40 + q] = (k < K) ? W[(size_t)k * N + n0 + q] : 0.0f;
        }
        __syncthreads();

        #pragma unroll
        for (int kk = 0; kk < 16; ++kk) {
            float a0 = As[kk * 64 + ty * 2 + 0];
            float a1 = As[kk * 64 + ty * 2 + 1];
            float wv[5];
            #pragma unroll
            for (int q = 0; q < 5; ++q) wv[q] = Bs[kk * 40 + tx * 5 + q];
            #pragma unroll
            for (int q = 0; q < 5; ++q) {
                acc[0][q] += a0 * wv[q];
                acc[1][q] += a1 * wv[q];
            }
        }
    }

    #pragma unroll
    for (int m = 0; m < 2; ++m) {
        int r = row0 + ty * 2 + m;
        #pragma unroll
        for (int q = 0; q < 5; ++q) {
            int n = n0 + tx * 5 + q;
            float v = acc[m][q] + bias[n];
            if (relu) v = fmaxf(v, 0.0f);
            Out[(size_t)r * N + n] = v;
        }
    }
}

// ===========================================================================
// Final: dnn linear dot + linear partials + combine + sigmoid
// ===========================================================================
__global__ void final_kernel(const float* __restrict__ b_lin,
                             const float* __restrict__ cin_lin_b,
                             const float* __restrict__ dnn_lin_w,
                             const float* __restrict__ dnn_lin_b,
                             const float* __restrict__ pred_b,
                             float* __restrict__ out) {
    const int b = blockIdx.x;
    const int tid = threadIdx.x;
    float acc = 0.0f;
    for (int k = tid; k < 400; k += 128)
        acc += g_h1[(size_t)b * 400 + k] * dnn_lin_w[k];
    for (int f = tid; f < 27; f += 128)
        acc += g_linpart[f * Bsz + b];
    __shared__ float red[128];
    red[tid] = acc;
    __syncthreads();
    for (int s = 64; s > 0; s >>= 1) {
        if (tid < s) red[tid] += red[tid + s];
        __syncthreads();
    }
    if (tid == 0) {
        float z = red[0] + b_lin[0]
                + g_cinlogit[b] + cin_lin_b[0]
                + dnn_lin_b[0] + pred_b[0];
        out[b] = 1.0f / (1.0f + expf(-z));
    }
}

// ===========================================================================
// host launcher
// ===========================================================================
extern "C" void kernel_launch(void* const* d_in, const int* in_sizes, int n_in,
                              void* d_out, int out_size) {
    const float* x         = (const float*)d_in[0];
    const float* w_lin     = (const float*)d_in[1];
    const float* b_lin     = (const float*)d_in[2];
    const float* W_num     = (const float*)d_in[3];
    const float* W_cat     = (const float*)d_in[4];
    const float* cin_w0    = (const float*)d_in[5];
    const float* cin_b0    = (const float*)d_in[6];
    const float* cin_w1    = (const float*)d_in[7];
    const float* cin_b1    = (const float*)d_in[8];
    const float* cin_w2    = (const float*)d_in[9];
    const float* cin_b2    = (const float*)d_in[10];
    const float* cin_lin_w = (const float*)d_in[11];
    const float* cin_lin_b = (const float*)d_in[12];
    const float* dnn_w0    = (const float*)d_in[13];
    const float* dnn_b0    = (const float*)d_in[14];
    const float* dnn_w1    = (const float*)d_in[15];
    const float* dnn_b1    = (const float*)d_in[16];
    const float* dnn_lin_w = (const float*)d_in[17];
    const float* dnn_lin_b = (const float*)d_in[18];
    const float* pred_b    = (const float*)d_in[19];
    float* out = (float*)d_out;

    float *p_E_dm, *p_E_flat, *p_h0, *p_h1, *p_pA, *p_pB, *p_pool2;
    cudaGetSymbolAddress((void**)&p_E_dm,   g_E_dm);
    cudaGetSymbolAddress((void**)&p_E_flat, g_E_flat);
    cudaGetSymbolAddress((void**)&p_h0,     g_h0);
    cudaGetSymbolAddress((void**)&p_h1,     g_h1);
    cudaGetSymbolAddress((void**)&p_pA,     g_pA);
    cudaGetSymbolAddress((void**)&p_pB,     g_pB);
    cudaGetSymbolAddress((void**)&p_pool2,  g_pool2);

    __nv_bfloat16 *p_W0hi, *p_W0lo, *p_W2hi, *p_W2lo;
    __half *p_W1;
    cudaGetSymbolAddress((void**)&p_W0hi, g_W0hi);
    cudaGetSymbolAddress((void**)&p_W0lo, g_W0lo);
    cudaGetSymbolAddress((void**)&p_W1,   g_W1);
    cudaGetSymbolAddress((void**)&p_W2hi, g_W2hi);
    cudaGetSymbolAddress((void**)&p_W2lo, g_W2lo);

    const int SM_SYM = 64 * 39 * 4 + 2 * (2 * 2 * B_HALF48) + KPER0 * 4;        // 97600
    const int SM_F16 = ((64 * 31 * 4 + 64 * 39 * 4 + 127) / 128) * 128
                     + 2 * (2 * B_HALF48) + KPER1 * 4;                           // 65408
    const int SM_P2  = 2 * (2 * 64 * 20 * 4) + 2 * (2 * 2 * B_HALF48);           // 106496
    cudaFuncSetAttribute(cin_sym,          cudaFuncAttributeMaxDynamicSharedMemorySize, SM_SYM);
    cudaFuncSetAttribute(cin_f16<SPLIT0>,  cudaFuncAttributeMaxDynamicSharedMemorySize, SM_F16);
    cudaFuncSetAttribute(gemm_p2,          cudaFuncAttributeMaxDynamicSharedMemorySize, SM_P2);

    const int ROWB = Rrows / 64;   // 160

    convert_w0_sym<<<(KPAD0 * NPAD + 255) / 256, 256>>>(cin_w0, p_W0hi, p_W0lo);      // 0
    numeric_kernel<<<Bsz / 128, 128>>>(x, w_lin, W_num);                              // 1
    cat_kernel<<<dim3(Bsz / 128, NUM_CAT), 256>>>(x, w_lin, W_cat);                   // 2
    cin_sym<<<dim3(ROWB, SPLIT0), 256, SM_SYM>>>(p_W0hi, p_W0lo, p_pA);               // 3 <- capture
    convert_w_f16<<<(KPAD1 * NPAD + 255) / 256, 256>>>(cin_w1, p_W1);                 // 4
    cin_f16<SPLIT0><<<dim3(ROWB, SPLIT1), 256, SM_F16>>>(p_pA, cin_b0, p_W1, p_pB);   // 5
    convert_w2_bf<<<(KP2 * NPAD + 255) / 256, 256>>>(cin_w2, p_W2hi, p_W2lo);         // 6
    p_kernel<<<Bsz, 256>>>(cin_b1);                                                   // 7
    gemm_p2<<<dim3(Bsz / 64, P2SPLIT), 256, SM_P2>>>(p_W2hi, p_W2lo, p_pool2);        // 8
    pool_kernel<<<Bsz, 256>>>(cin_lin_w, cin_b0, cin_b1, cin_b2);                     // 9
    dim3 dgrid(Bsz / 64, 400 / 40);
    dnn_gemm<<<dgrid, 256>>>(p_E_flat, dnn_w0, dnn_b0, p_h0, Mfld * Demb, 1);         // 10
    dnn_gemm<<<dgrid, 256>>>(p_h0, dnn_w1, dnn_b1, p_h1, 400, 1);                     // 11
    final_kernel<<<Bsz, 128>>>(b_lin, cin_lin_b, dnn_lin_w, dnn_lin_b, pred_b, out);  // 12
}